// round 2
// baseline (speedup 1.0000x reference)
#include <cuda_runtime.h>
#include <math.h>

// Problem constants
#define Bz 2
#define Sz 4096
#define Dz 1024
#define Fz 4096
#define Mz (Bz * Sz)   // 8192

// ---------------------------------------------------------------------------
// Scratch (allocation-free: __device__ globals)
// ---------------------------------------------------------------------------
__device__ float g_Q [(size_t)Mz * Dz];       // 33.5 MB
__device__ float g_K [(size_t)Mz * Dz];
__device__ float g_V [(size_t)Mz * Dz];
__device__ float g_A [(size_t)Mz * 2 * Dz];   // 67 MB (a_real | a_imag)
__device__ float g_G [(size_t)Mz * Dz];
__device__ float g_Y [(size_t)Mz * Dz];       // real(y) after gating
__device__ float g_Yo[(size_t)Mz * Dz];       // y @ Wo
__device__ float g_U [(size_t)Mz * Dz];       // LN1 output (residual stream)
__device__ float g_H [(size_t)Mz * Fz];       // 134 MB FFN hidden
__device__ float g_O2[(size_t)Mz * Dz];       // FFN output

// ---------------------------------------------------------------------------
// FP32 tiled GEMM: C[M,N] = A[M,K] @ B[K,N] (+bias) (+gelu)
// 128x128 block tile, 16 K-tile, 8x8 per thread, 256 threads.
// act: 0 = none, 1 = +bias, 2 = +bias then tanh-gelu
// ---------------------------------------------------------------------------
__global__ __launch_bounds__(256) void sgemm_k(
    const float* __restrict__ A, const float* __restrict__ Bm,
    const float* __restrict__ bias, float* __restrict__ C,
    int M, int N, int K, int act)
{
    __shared__ float As[16][128];
    __shared__ float Bs[16][128];

    const int bm  = blockIdx.y * 128;
    const int bn  = blockIdx.x * 128;
    const int tid = threadIdx.x;
    const int tx  = tid & 15;   // 0..15 -> N direction
    const int ty  = tid >> 4;   // 0..15 -> M direction

    float acc[8][8];
#pragma unroll
    for (int i = 0; i < 8; i++)
#pragma unroll
        for (int j = 0; j < 8; j++) acc[i][j] = 0.0f;

    const int aRow0 = tid >> 2;        // 0..63
    const int aCol4 = (tid & 3) * 4;   // 0,4,8,12
    const int bRow0 = tid >> 5;        // 0..7
    const int bCol4 = (tid & 31) * 4;  // 0..124

    for (int k0 = 0; k0 < K; k0 += 16) {
        // A tile (128 x 16), stored transposed As[k][m]
#pragma unroll
        for (int p = 0; p < 2; p++) {
            int row = aRow0 + p * 64;
            float4 va = *reinterpret_cast<const float4*>(
                &A[(size_t)(bm + row) * K + k0 + aCol4]);
            As[aCol4 + 0][row] = va.x;
            As[aCol4 + 1][row] = va.y;
            As[aCol4 + 2][row] = va.z;
            As[aCol4 + 3][row] = va.w;
        }
        // B tile (16 x 128)
#pragma unroll
        for (int p = 0; p < 2; p++) {
            int row = bRow0 + p * 8;
            float4 vb = *reinterpret_cast<const float4*>(
                &Bm[(size_t)(k0 + row) * N + bn + bCol4]);
            *reinterpret_cast<float4*>(&Bs[row][bCol4]) = vb;
        }
        __syncthreads();

#pragma unroll
        for (int k = 0; k < 16; k++) {
            float ra[8], rb[8];
            *reinterpret_cast<float4*>(ra)     = *reinterpret_cast<const float4*>(&As[k][ty * 8]);
            *reinterpret_cast<float4*>(ra + 4) = *reinterpret_cast<const float4*>(&As[k][ty * 8 + 4]);
            *reinterpret_cast<float4*>(rb)     = *reinterpret_cast<const float4*>(&Bs[k][tx * 8]);
            *reinterpret_cast<float4*>(rb + 4) = *reinterpret_cast<const float4*>(&Bs[k][tx * 8 + 4]);
#pragma unroll
            for (int i = 0; i < 8; i++)
#pragma unroll
                for (int j = 0; j < 8; j++)
                    acc[i][j] = fmaf(ra[i], rb[j], acc[i][j]);
        }
        __syncthreads();
    }

    // Epilogue
#pragma unroll
    for (int i = 0; i < 8; i++) {
        int row = bm + ty * 8 + i;
#pragma unroll
        for (int j = 0; j < 8; j++) {
            int col = bn + tx * 8 + j;
            float v = acc[i][j];
            if (act >= 1) v += bias[col];
            if (act == 2) {
                // JAX default gelu (approximate=True, tanh form)
                float x3 = v * v * v;
                v = 0.5f * v * (1.0f + tanhf(0.7978845608028654f * (v + 0.044715f * x3)));
            }
            C[(size_t)row * N + col] = v;
        }
    }
}

// ---------------------------------------------------------------------------
// GateLoop scan: per (b,d) channel, sequential over t.
//   a_c   = sigmoid(|a|) * a/|a|                (complex, |a_c|<1)
//   h_t   = a_c * h_{t-1} + k_t*v_t             (complex, kv real)
//   y_t   = q_t * Re(h_t) * silu(g_t)           (only real part survives @Wo)
// ---------------------------------------------------------------------------
__global__ void gateloop_kernel(
    const float* __restrict__ q, const float* __restrict__ k,
    const float* __restrict__ v, const float* __restrict__ a,
    const float* __restrict__ g, float* __restrict__ y)
{
    int c = blockIdx.x * blockDim.x + threadIdx.x;  // 0..B*D-1
    if (c >= Bz * Dz) return;
    int b = c >> 10;          // / Dz
    int d = c & (Dz - 1);     // % Dz
    size_t base  = (size_t)b * Sz * Dz + d;
    size_t abase = (size_t)b * Sz * 2 * Dz + d;

    float hr = 0.0f, hi = 0.0f;
    for (int t = 0; t < Sz; t++) {
        size_t i  = base  + (size_t)t * Dz;
        size_t ia = abase + (size_t)t * 2 * Dz;
        float ar = a[ia];
        float ai = a[ia + Dz];
        float mag = sqrtf(fmaf(ar, ar, ai * ai));
        float s   = 1.0f / (1.0f + __expf(-mag));   // sigmoid(|a|)
        float inv = s / fmaxf(mag, 1e-30f);
        float arr = ar * inv;
        float aii = ai * inv;
        float kv  = k[i] * v[i];
        float nhr = fmaf(arr, hr, fmaf(-aii, hi, kv));
        float nhi = fmaf(arr, hi, aii * hr);
        hr = nhr; hi = nhi;
        float gg  = g[i];
        float sil = gg / (1.0f + __expf(-gg));      // silu(g), g is real
        y[i] = q[i] * hr * sil;
    }
}

// ---------------------------------------------------------------------------
// out = LayerNorm(x + res) * scale + bias ; one block per row, 256 threads
// ---------------------------------------------------------------------------
__global__ __launch_bounds__(256) void add_ln_kernel(
    const float* __restrict__ x, const float* __restrict__ res,
    const float* __restrict__ scale, const float* __restrict__ bias,
    float* __restrict__ out)
{
    __shared__ float red[8];
    int row = blockIdx.x;
    int tid = threadIdx.x;
    const float* xr = x   + (size_t)row * Dz;
    const float* rr = res + (size_t)row * Dz;

    float vals[4];
    float sum = 0.0f;
#pragma unroll
    for (int j = 0; j < 4; j++) {
        int col = tid + j * 256;
        vals[j] = xr[col] + rr[col];
        sum += vals[j];
    }
#pragma unroll
    for (int o = 16; o > 0; o >>= 1) sum += __shfl_xor_sync(0xffffffffu, sum, o);
    if ((tid & 31) == 0) red[tid >> 5] = sum;
    __syncthreads();
    float tot = 0.0f;
#pragma unroll
    for (int w = 0; w < 8; w++) tot += red[w];
    float mean = tot * (1.0f / (float)Dz);

    float vs = 0.0f;
#pragma unroll
    for (int j = 0; j < 4; j++) {
        float dlt = vals[j] - mean;
        vs += dlt * dlt;
    }
#pragma unroll
    for (int o = 16; o > 0; o >>= 1) vs += __shfl_xor_sync(0xffffffffu, vs, o);
    __syncthreads();   // protect red[] reuse
    if ((tid & 31) == 0) red[tid >> 5] = vs;
    __syncthreads();
    float vtot = 0.0f;
#pragma unroll
    for (int w = 0; w < 8; w++) vtot += red[w];
    float var  = vtot * (1.0f / (float)Dz);
    float rstd = rsqrtf(var + 1e-6f);

#pragma unroll
    for (int j = 0; j < 4; j++) {
        int col = tid + j * 256;
        out[(size_t)row * Dz + col] =
            (vals[j] - mean) * rstd * scale[col] + bias[col];
    }
}

// ---------------------------------------------------------------------------
// Launch
// ---------------------------------------------------------------------------
extern "C" void kernel_launch(void* const* d_in, const int* in_sizes, int n_in,
                              void* d_out, int out_size)
{
    const float* x    = (const float*)d_in[0];
    const float* Wq   = (const float*)d_in[1];
    const float* Wk   = (const float*)d_in[2];
    const float* Wv   = (const float*)d_in[3];
    const float* Wa   = (const float*)d_in[4];
    const float* Wg   = (const float*)d_in[5];
    const float* Wo   = (const float*)d_in[6];
    const float* ln1s = (const float*)d_in[7];
    const float* ln1b = (const float*)d_in[8];
    const float* W1   = (const float*)d_in[9];
    const float* b1   = (const float*)d_in[10];
    const float* W2   = (const float*)d_in[11];
    const float* b2   = (const float*)d_in[12];
    const float* ln2s = (const float*)d_in[13];
    const float* ln2b = (const float*)d_in[14];
    float* out = (float*)d_out;

    float *Q, *K, *V, *A, *G, *Y, *Yo, *U, *H, *O2;
    cudaGetSymbolAddress((void**)&Q,  g_Q);
    cudaGetSymbolAddress((void**)&K,  g_K);
    cudaGetSymbolAddress((void**)&V,  g_V);
    cudaGetSymbolAddress((void**)&A,  g_A);
    cudaGetSymbolAddress((void**)&G,  g_G);
    cudaGetSymbolAddress((void**)&Y,  g_Y);
    cudaGetSymbolAddress((void**)&Yo, g_Yo);
    cudaGetSymbolAddress((void**)&U,  g_U);
    cudaGetSymbolAddress((void**)&H,  g_H);
    cudaGetSymbolAddress((void**)&O2, g_O2);

    dim3 blk(256);
    dim3 gD (Dz / 128,     Mz / 128);   // N=1024
    dim3 g2D(2 * Dz / 128, Mz / 128);   // N=2048
    dim3 gF (Fz / 128,     Mz / 128);   // N=4096

    // Projections
    sgemm_k<<<gD,  blk>>>(x, Wq, nullptr, Q, Mz, Dz,     Dz, 0);
    sgemm_k<<<gD,  blk>>>(x, Wk, nullptr, K, Mz, Dz,     Dz, 0);
    sgemm_k<<<gD,  blk>>>(x, Wv, nullptr, V, Mz, Dz,     Dz, 0);
    sgemm_k<<<g2D, blk>>>(x, Wa, nullptr, A, Mz, 2 * Dz, Dz, 0);
    sgemm_k<<<gD,  blk>>>(x, Wg, nullptr, G, Mz, Dz,     Dz, 0);

    // Gated complex scan (real output)
    gateloop_kernel<<<(Bz * Dz) / 256, 256>>>(Q, K, V, A, G, Y);

    // Output projection + residual + LN1
    sgemm_k<<<gD, blk>>>(Y, Wo, nullptr, Yo, Mz, Dz, Dz, 0);
    add_ln_kernel<<<Mz, 256>>>(Yo, x, ln1s, ln1b, U);

    // FFN
    sgemm_k<<<gF, blk>>>(U, W1, b1, H,  Mz, Fz, Dz, 2);  // +bias, gelu
    sgemm_k<<<gD, blk>>>(H, W2, b2, O2, Mz, Dz, Fz, 1);  // +bias

    // Residual + LN2 -> out
    add_ln_kernel<<<Mz, 256>>>(O2, U, ln2s, ln2b, out);
}

// round 4
// speedup vs baseline: 5.3143x; 5.3143x over previous
#include <cuda_runtime.h>
#include <cuda_bf16.h>
#include <math.h>
#include <stdint.h>

#define Bz 2
#define Sz 4096
#define Dz 1024
#define Fz 4096
#define Mz (Bz * Sz)
#define NP 6144
#define NCH 32
#define CLEN 128

// ------------------------- scratch --------------------------------------
__device__ __align__(256) float g_P [(size_t)Mz * NP];
__device__ __align__(256) float g_Yo[(size_t)Mz * Dz];
__device__ __align__(256) float g_U [(size_t)Mz * Dz];
__device__ __align__(256) float g_O2[(size_t)Mz * Dz];
__device__ __align__(256) __nv_bfloat16 g_xh[(size_t)Mz * Dz], g_xl[(size_t)Mz * Dz];
__device__ __align__(256) __nv_bfloat16 g_yh[(size_t)Mz * Dz], g_yl[(size_t)Mz * Dz];
__device__ __align__(256) __nv_bfloat16 g_uh[(size_t)Mz * Dz], g_ul[(size_t)Mz * Dz];
__device__ __align__(256) __nv_bfloat16 g_Hh[(size_t)Mz * Fz], g_Hl[(size_t)Mz * Fz];
__device__ __align__(256) __nv_bfloat16 g_Wc_h[(size_t)NP * Dz], g_Wc_l[(size_t)NP * Dz];
__device__ __align__(256) __nv_bfloat16 g_Wo_h[(size_t)Dz * Dz], g_Wo_l[(size_t)Dz * Dz];
__device__ __align__(256) __nv_bfloat16 g_W1_h[(size_t)Fz * Dz], g_W1_l[(size_t)Fz * Dz];
__device__ __align__(256) __nv_bfloat16 g_W2_h[(size_t)Dz * Fz], g_W2_l[(size_t)Dz * Fz];
__device__ float s_apr[65536], s_api[65536], s_hr[65536], s_hi[65536];
__device__ float s_cr[65536], s_ci[65536];

// ------------------------- asm helpers ----------------------------------
__device__ __forceinline__ uint32_t smem_u32(const void* p) {
    uint32_t a;
    asm("{ .reg .u64 t; cvta.to.shared.u64 t, %1; cvt.u32.u64 %0, t; }" : "=r"(a) : "l"(p));
    return a;
}
__device__ __forceinline__ void cp16(uint32_t dst, const void* src) {
    asm volatile("cp.async.cg.shared.global [%0], [%1], 16;" :: "r"(dst), "l"(src) : "memory");
}
__device__ __forceinline__ void ldsm4(uint32_t* r, uint32_t a) {
    asm volatile("ldmatrix.sync.aligned.m8n8.x4.shared.b16 {%0,%1,%2,%3}, [%4];"
                 : "=r"(r[0]), "=r"(r[1]), "=r"(r[2]), "=r"(r[3]) : "r"(a));
}
__device__ __forceinline__ void mma16816(float* c, const uint32_t* a, uint32_t b0, uint32_t b1) {
    asm volatile(
        "mma.sync.aligned.m16n8k16.row.col.f32.bf16.bf16.f32 "
        "{%0,%1,%2,%3}, {%4,%5,%6,%7}, {%8,%9}, {%0,%1,%2,%3};"
        : "+f"(c[0]), "+f"(c[1]), "+f"(c[2]), "+f"(c[3])
        : "r"(a[0]), "r"(a[1]), "r"(a[2]), "r"(a[3]), "r"(b0), "r"(b1));
}

// ------------------------- bf16x3 mma.sync GEMM --------------------------
// C[M,N] = A[M,K] @ Bt[N,K]^T.  CTA 128x128, 8 warps (64x32), Kc=64, 3 stages.
#define STG 65536
#define GEMM_SMEM (3 * STG)

__global__ void __launch_bounds__(256, 1) gemm_mma(
    const __nv_bfloat16* __restrict__ Ah, const __nv_bfloat16* __restrict__ Al,
    const __nv_bfloat16* __restrict__ Bh, const __nv_bfloat16* __restrict__ Bl,
    const float* __restrict__ bias, float* __restrict__ Cf,
    __nv_bfloat16* __restrict__ Chi, __nv_bfloat16* __restrict__ Clo,
    int N, int K, int act)
{
    extern __shared__ __align__(1024) char dsm[];
    const uint32_t smb = smem_u32(dsm);
    const int tid = threadIdx.x;
    const int bm = blockIdx.y * 128, bn = blockIdx.x * 128;
    const int wid = tid >> 5, L = tid & 31;
    const int wm = (wid >> 2) * 64;   // 0 / 64
    const int wn = (wid & 3) * 32;    // 0..96

    float acc[4][4][4];
#pragma unroll
    for (int i = 0; i < 4; i++)
#pragma unroll
        for (int j = 0; j < 4; j++)
#pragma unroll
            for (int q = 0; q < 4; q++) acc[i][j][q] = 0.f;

    // per-lane ldmatrix address components
    const int matid = L >> 3;
    const int rA = (matid & 1) * 8 + (L & 7);      // A: row-in-16 tile
    const int cA = matid >> 1;                     // A: k-16B-half select
    const int rB = (L >> 4) * 8 + (L & 7);         // B: row-in-16 tile
    const int cB = (L >> 3) & 1;
    const int x7 = L & 7;

    const int nkc = K / 64;
    // cp.async stage loader (16 x 16B per thread)
    auto load_stage = [&](int st, int kc) {
        uint32_t sb = smb + st * STG;
        size_t kb = (size_t)kc * 64;
#pragma unroll
        for (int t = 0; t < 4; t++) {
            int id = t * 256 + tid;            // 0..1023
            int row = id >> 3, ch = id & 7;
            uint32_t dst = (uint32_t)(row * 128 + ((ch ^ (row & 7)) * 16));
            size_t sA = (size_t)(bm + row) * K + kb + ch * 8;
            size_t sB = (size_t)(bn + row) * K + kb + ch * 8;
            cp16(sb + dst,          Ah + sA);
            cp16(sb + 16384 + dst,  Al + sA);
            cp16(sb + 32768 + dst,  Bh + sB);
            cp16(sb + 49152 + dst,  Bl + sB);
        }
    };

#pragma unroll
    for (int s = 0; s < 3; s++) {
        load_stage(s, s);
        asm volatile("cp.async.commit_group;" ::: "memory");
    }

    for (int kc = 0; kc < nkc; kc++) {
        asm volatile("cp.async.wait_group 2;" ::: "memory");
        __syncthreads();
        uint32_t sb = smb + (kc % 3) * STG;
        uint32_t sAh = sb, sAl = sb + 16384, sBh = sb + 32768, sBl = sb + 49152;
#pragma unroll
        for (int ks = 0; ks < 4; ks++) {
            uint32_t ah[4][4], al[4][4], bh[2][4], bl[2][4];
            int chA = (ks * 2 + cA) ^ x7;
            int chB = (ks * 2 + cB) ^ x7;
#pragma unroll
            for (int mt = 0; mt < 4; mt++) {
                uint32_t off = (uint32_t)((wm + mt * 16 + rA) * 128 + chA * 16);
                ldsm4(ah[mt], sAh + off);
                ldsm4(al[mt], sAl + off);
            }
#pragma unroll
            for (int bt = 0; bt < 2; bt++) {
                uint32_t off = (uint32_t)((wn + bt * 16 + rB) * 128 + chB * 16);
                ldsm4(bh[bt], sBh + off);
                ldsm4(bl[bt], sBl + off);
            }
#pragma unroll
            for (int mt = 0; mt < 4; mt++)
#pragma unroll
                for (int nt = 0; nt < 4; nt++) {
                    int bt = nt >> 1, j = (nt & 1) * 2;
                    mma16816(acc[mt][nt], ah[mt], bh[bt][j], bh[bt][j + 1]);
                    mma16816(acc[mt][nt], ah[mt], bl[bt][j], bl[bt][j + 1]);
                    mma16816(acc[mt][nt], al[mt], bh[bt][j], bh[bt][j + 1]);
                }
        }
        __syncthreads();
        if (kc + 3 < nkc) load_stage(kc % 3, kc + 3);
        asm volatile("cp.async.commit_group;" ::: "memory");
    }

    // epilogue
    float bc0[4], bc1[4];
#pragma unroll
    for (int nt = 0; nt < 4; nt++) {
        int c = bn + wn + nt * 8 + (L & 3) * 2;
        bc0[nt] = (act > 0) ? bias[c] : 0.f;
        bc1[nt] = (act > 0) ? bias[c + 1] : 0.f;
    }
#pragma unroll
    for (int mt = 0; mt < 4; mt++)
#pragma unroll
        for (int nt = 0; nt < 4; nt++) {
            int c0 = bn + wn + nt * 8 + (L & 3) * 2;
#pragma unroll
            for (int h = 0; h < 2; h++) {
                int row = bm + wm + mt * 16 + (L >> 2) + h * 8;
                float v0 = acc[mt][nt][h * 2 + 0] + bc0[nt];
                float v1 = acc[mt][nt][h * 2 + 1] + bc1[nt];
                if (act == 2) {
                    float t0 = v0 * v0 * v0, t1 = v1 * v1 * v1;
                    v0 = 0.5f * v0 * (1.f + tanhf(0.7978845608028654f * (v0 + 0.044715f * t0)));
                    v1 = 0.5f * v1 * (1.f + tanhf(0.7978845608028654f * (v1 + 0.044715f * t1)));
                }
                size_t idx = (size_t)row * N + c0;
                if (Cf) *reinterpret_cast<float2*>(Cf + idx) = make_float2(v0, v1);
                if (Chi) {
                    __nv_bfloat162 hh, ll;
                    hh.x = __float2bfloat16_rn(v0);
                    hh.y = __float2bfloat16_rn(v1);
                    ll.x = __float2bfloat16_rn(v0 - __bfloat162float(hh.x));
                    ll.y = __float2bfloat16_rn(v1 - __bfloat162float(hh.y));
                    *reinterpret_cast<__nv_bfloat162*>(Chi + idx) = hh;
                    *reinterpret_cast<__nv_bfloat162*>(Clo + idx) = ll;
                }
            }
        }
}

// ------------------------- small kernels ---------------------------------
__global__ void conv_split(const float* __restrict__ in, __nv_bfloat16* __restrict__ hi,
                           __nv_bfloat16* __restrict__ lo, size_t n4) {
    size_t i = (size_t)blockIdx.x * blockDim.x + threadIdx.x;
    if (i >= n4) return;
    float4 v = ((const float4*)in)[i];
    float vv[4] = {v.x, v.y, v.z, v.w};
#pragma unroll
    for (int j = 0; j < 4; j++) {
        __nv_bfloat16 h = __float2bfloat16_rn(vv[j]);
        hi[i * 4 + j] = h;
        lo[i * 4 + j] = __float2bfloat16_rn(vv[j] - __bfloat162float(h));
    }
}

__global__ void wconv_t(const float* __restrict__ W, __nv_bfloat16* __restrict__ Th,
                        __nv_bfloat16* __restrict__ Tl, int K, int N) {
    __shared__ float t[32][33];
    int n0 = blockIdx.x * 32, k0 = blockIdx.y * 32;
    int tx = threadIdx.x, ty = threadIdx.y;
#pragma unroll
    for (int j = 0; j < 4; j++)
        t[ty + j * 8][tx] = W[(size_t)(k0 + ty + j * 8) * N + n0 + tx];
    __syncthreads();
#pragma unroll
    for (int j = 0; j < 4; j++) {
        float v = t[tx][ty + j * 8];
        __nv_bfloat16 h = __float2bfloat16_rn(v);
        size_t idx = (size_t)(n0 + ty + j * 8) * K + k0 + tx;
        Th[idx] = h;
        Tl[idx] = __float2bfloat16_rn(v - __bfloat162float(h));
    }
}

__global__ void scan_p1(const float* __restrict__ P) {
    int idx = blockIdx.x * blockDim.x + threadIdx.x;
    int ch = idx & 2047, ck = idx >> 11;
    int b = ch >> 10, d = ch & 1023;
    const float* p = P + ((size_t)(b * Sz + ck * CLEN)) * NP;
    float hr = 0, hi = 0, pr = 1, pi = 0;
    for (int t = 0; t < CLEN; t++) {
        const float* r = p + (size_t)t * NP;
        float ar = r[3072 + d], ai = r[4096 + d];
        float kv = r[1024 + d] * r[2048 + d];
        float mag = sqrtf(fmaf(ar, ar, ai * ai));
        float s = 1.f / (1.f + __expf(-mag));
        float inv = s / fmaxf(mag, 1e-30f);
        float arr = ar * inv, aii = ai * inv;
        float nhr = fmaf(arr, hr, fmaf(-aii, hi, kv));
        float nhi = fmaf(arr, hi, aii * hr);
        hr = nhr; hi = nhi;
        float npr = arr * pr - aii * pi, npi = arr * pi + aii * pr;
        pr = npr; pi = npi;
    }
    s_apr[idx] = pr; s_api[idx] = pi; s_hr[idx] = hr; s_hi[idx] = hi;
}

__global__ void scan_p2() {
    int ch = blockIdx.x * blockDim.x + threadIdx.x;
    if (ch >= 2048) return;
    float cr = 0, ci = 0;
    for (int ck = 0; ck < NCH; ck++) {
        int i = ck * 2048 + ch;
        s_cr[i] = cr; s_ci[i] = ci;
        float pr = s_apr[i], pi = s_api[i];
        float ncr = fmaf(pr, cr, -pi * ci) + s_hr[i];
        float nci = fmaf(pr, ci,  pi * cr) + s_hi[i];
        cr = ncr; ci = nci;
    }
}

__global__ void scan_p3(const float* __restrict__ P,
                        __nv_bfloat16* __restrict__ yh, __nv_bfloat16* __restrict__ yl) {
    int idx = blockIdx.x * blockDim.x + threadIdx.x;
    int ch = idx & 2047, ck = idx >> 11;
    int b = ch >> 10, d = ch & 1023;
    size_t row0 = (size_t)(b * Sz + ck * CLEN);
    const float* p = P + row0 * NP;
    float hr = s_cr[idx], hi = s_ci[idx];
    for (int t = 0; t < CLEN; t++) {
        const float* r = p + (size_t)t * NP;
        float ar = r[3072 + d], ai = r[4096 + d];
        float kv = r[1024 + d] * r[2048 + d];
        float mag = sqrtf(fmaf(ar, ar, ai * ai));
        float s = 1.f / (1.f + __expf(-mag));
        float inv = s / fmaxf(mag, 1e-30f);
        float arr = ar * inv, aii = ai * inv;
        float nhr = fmaf(arr, hr, fmaf(-aii, hi, kv));
        float nhi = fmaf(arr, hi, aii * hr);
        hr = nhr; hi = nhi;
        float g = r[5120 + d];
        float sil = g / (1.f + __expf(-g));
        float yv = r[d] * hr * sil;
        __nv_bfloat16 h16 = __float2bfloat16_rn(yv);
        size_t o = (row0 + t) * Dz + d;
        yh[o] = h16;
        yl[o] = __float2bfloat16_rn(yv - __bfloat162float(h16));
    }
}

__global__ __launch_bounds__(256) void add_ln_kernel(
    const float* __restrict__ x, const float* __restrict__ res,
    const float* __restrict__ scale, const float* __restrict__ bias,
    float* __restrict__ out, __nv_bfloat16* __restrict__ oh, __nv_bfloat16* __restrict__ ol)
{
    __shared__ float red[8];
    int row = blockIdx.x, tid = threadIdx.x;
    const float* xr = x + (size_t)row * Dz;
    const float* rr = res + (size_t)row * Dz;
    float vals[4], sum = 0.f;
#pragma unroll
    for (int j = 0; j < 4; j++) { vals[j] = xr[tid + j * 256] + rr[tid + j * 256]; sum += vals[j]; }
#pragma unroll
    for (int o = 16; o > 0; o >>= 1) sum += __shfl_xor_sync(~0u, sum, o);
    if ((tid & 31) == 0) red[tid >> 5] = sum;
    __syncthreads();
    float tot = 0.f;
#pragma unroll
    for (int w = 0; w < 8; w++) tot += red[w];
    float mean = tot * (1.f / Dz);
    float vs = 0.f;
#pragma unroll
    for (int j = 0; j < 4; j++) { float dd = vals[j] - mean; vs += dd * dd; }
#pragma unroll
    for (int o = 16; o > 0; o >>= 1) vs += __shfl_xor_sync(~0u, vs, o);
    __syncthreads();
    if ((tid & 31) == 0) red[tid >> 5] = vs;
    __syncthreads();
    float vt = 0.f;
#pragma unroll
    for (int w = 0; w < 8; w++) vt += red[w];
    float rstd = rsqrtf(vt * (1.f / Dz) + 1e-6f);
#pragma unroll
    for (int j = 0; j < 4; j++) {
        int col = tid + j * 256;
        float v = (vals[j] - mean) * rstd * scale[col] + bias[col];
        size_t idx = (size_t)row * Dz + col;
        out[idx] = v;
        if (oh) {
            __nv_bfloat16 h = __float2bfloat16_rn(v);
            oh[idx] = h;
            ol[idx] = __float2bfloat16_rn(v - __bfloat162float(h));
        }
    }
}

// ------------------------- host ------------------------------------------
static void rungemm(const __nv_bfloat16* Ah, const __nv_bfloat16* Al, int K,
                    const __nv_bfloat16* Bh, const __nv_bfloat16* Bl, int N,
                    const float* bias, float* Cf, __nv_bfloat16* Chi, __nv_bfloat16* Clo, int act) {
    dim3 g(N / 128, Mz / 128);
    gemm_mma<<<g, 256, GEMM_SMEM>>>(Ah, Al, Bh, Bl, bias, Cf, Chi, Clo, N, K, act);
}

extern "C" void kernel_launch(void* const* d_in, const int* in_sizes, int n_in,
                              void* d_out, int out_size)
{
    const float* x    = (const float*)d_in[0];
    const float* Wq   = (const float*)d_in[1];
    const float* Wk   = (const float*)d_in[2];
    const float* Wv   = (const float*)d_in[3];
    const float* Wa   = (const float*)d_in[4];
    const float* Wg   = (const float*)d_in[5];
    const float* Wo   = (const float*)d_in[6];
    const float* ln1s = (const float*)d_in[7];
    const float* ln1b = (const float*)d_in[8];
    const float* W1   = (const float*)d_in[9];
    const float* b1   = (const float*)d_in[10];
    const float* W2   = (const float*)d_in[11];
    const float* b2   = (const float*)d_in[12];
    const float* ln2s = (const float*)d_in[13];
    const float* ln2b = (const float*)d_in[14];
    float* out = (float*)d_out;

    static int inited = 0;
    if (!inited) {
        cudaFuncSetAttribute(gemm_mma, cudaFuncAttributeMaxDynamicSharedMemorySize, GEMM_SMEM);
        inited = 1;
    }

    float *P, *Yo, *U, *O2;
    __nv_bfloat16 *xh, *xl, *yh, *yl, *uh, *ul, *Hh, *Hl;
    __nv_bfloat16 *WcH, *WcL, *WoH, *WoL, *W1H, *W1L, *W2H, *W2L;
    cudaGetSymbolAddress((void**)&P,  g_P);
    cudaGetSymbolAddress((void**)&Yo, g_Yo);
    cudaGetSymbolAddress((void**)&U,  g_U);
    cudaGetSymbolAddress((void**)&O2, g_O2);
    cudaGetSymbolAddress((void**)&xh, g_xh);  cudaGetSymbolAddress((void**)&xl, g_xl);
    cudaGetSymbolAddress((void**)&yh, g_yh);  cudaGetSymbolAddress((void**)&yl, g_yl);
    cudaGetSymbolAddress((void**)&uh, g_uh);  cudaGetSymbolAddress((void**)&ul, g_ul);
    cudaGetSymbolAddress((void**)&Hh, g_Hh);  cudaGetSymbolAddress((void**)&Hl, g_Hl);
    cudaGetSymbolAddress((void**)&WcH, g_Wc_h); cudaGetSymbolAddress((void**)&WcL, g_Wc_l);
    cudaGetSymbolAddress((void**)&WoH, g_Wo_h); cudaGetSymbolAddress((void**)&WoL, g_Wo_l);
    cudaGetSymbolAddress((void**)&W1H, g_W1_h); cudaGetSymbolAddress((void**)&W1L, g_W1_l);
    cudaGetSymbolAddress((void**)&W2H, g_W2_h); cudaGetSymbolAddress((void**)&W2L, g_W2_l);

    dim3 wb(32, 8);
    wconv_t<<<dim3(32, 32),  wb>>>(Wq, WcH,                     WcL,                     Dz, Dz);
    wconv_t<<<dim3(32, 32),  wb>>>(Wk, WcH + 1024 * 1024,       WcL + 1024 * 1024,       Dz, Dz);
    wconv_t<<<dim3(32, 32),  wb>>>(Wv, WcH + 2048 * 1024,       WcL + 2048 * 1024,       Dz, Dz);
    wconv_t<<<dim3(64, 32),  wb>>>(Wa, WcH + 3072 * 1024,       WcL + 3072 * 1024,       Dz, 2 * Dz);
    wconv_t<<<dim3(32, 32),  wb>>>(Wg, WcH + (size_t)5120 * 1024, WcL + (size_t)5120 * 1024, Dz, Dz);
    wconv_t<<<dim3(32, 32),  wb>>>(Wo, WoH, WoL, Dz, Dz);
    wconv_t<<<dim3(128, 32), wb>>>(W1, W1H, W1L, Dz, Fz);
    wconv_t<<<dim3(32, 128), wb>>>(W2, W2H, W2L, Fz, Dz);
    conv_split<<<(Mz * Dz / 4 + 255) / 256, 256>>>(x, xh, xl, (size_t)Mz * Dz / 4);

    // fused projections P = x @ [Wq|Wk|Wv|Wa|Wg]
    rungemm(xh, xl, Dz, WcH, WcL, NP, nullptr, P, nullptr, nullptr, 0);
    // chunked gate-loop scan
    scan_p1<<<256, 256>>>(P);
    scan_p2<<<8, 256>>>();
    scan_p3<<<256, 256>>>(P, yh, yl);
    // y @ Wo, +x, LN1
    rungemm(yh, yl, Dz, WoH, WoL, Dz, nullptr, Yo, nullptr, nullptr, 0);
    add_ln_kernel<<<Mz, 256>>>(Yo, x, ln1s, ln1b, U, uh, ul);
    // FFN
    rungemm(uh, ul, Dz, W1H, W1L, Fz, b1, nullptr, Hh, Hl, 2);
    rungemm(Hh, Hl, Fz, W2H, W2L, Dz, b2, O2, nullptr, nullptr, 1);
    add_ln_kernel<<<Mz, 256>>>(O2, U, ln2s, ln2b, out, nullptr, nullptr);
}

// round 5
// speedup vs baseline: 5.5861x; 1.0511x over previous
#include <cuda_runtime.h>
#include <cuda_bf16.h>
#include <math.h>
#include <stdint.h>

#define Bz 2
#define Sz 4096
#define Dz 1024
#define Fz 4096
#define Mz (Bz * Sz)
#define NP 6144
#define NCH 32
#define CLEN 128

// ------------------------- scratch --------------------------------------
__device__ __align__(256) float g_P [(size_t)Mz * NP];
__device__ __align__(256) float g_Yo[(size_t)Mz * Dz];
__device__ __align__(256) float g_U [(size_t)Mz * Dz];
__device__ __align__(256) float g_O2[(size_t)Mz * Dz];
__device__ __align__(256) __nv_bfloat16 g_xh[(size_t)Mz * Dz], g_xl[(size_t)Mz * Dz];
__device__ __align__(256) __nv_bfloat16 g_yh[(size_t)Mz * Dz], g_yl[(size_t)Mz * Dz];
__device__ __align__(256) __nv_bfloat16 g_uh[(size_t)Mz * Dz], g_ul[(size_t)Mz * Dz];
__device__ __align__(256) __nv_bfloat16 g_Hh[(size_t)Mz * Fz], g_Hl[(size_t)Mz * Fz];
__device__ __align__(256) __nv_bfloat16 g_Wc_h[(size_t)NP * Dz], g_Wc_l[(size_t)NP * Dz];
__device__ __align__(256) __nv_bfloat16 g_Wo_h[(size_t)Dz * Dz], g_Wo_l[(size_t)Dz * Dz];
__device__ __align__(256) __nv_bfloat16 g_W1_h[(size_t)Fz * Dz], g_W1_l[(size_t)Fz * Dz];
__device__ __align__(256) __nv_bfloat16 g_W2_h[(size_t)Dz * Fz], g_W2_l[(size_t)Dz * Fz];
__device__ float s_apr[65536], s_api[65536], s_hr[65536], s_hi[65536];
__device__ float s_cr[65536], s_ci[65536];

// ------------------------- asm helpers ----------------------------------
__device__ __forceinline__ uint32_t smem_u32(const void* p) {
    uint32_t a;
    asm("{ .reg .u64 t; cvta.to.shared.u64 t, %1; cvt.u32.u64 %0, t; }" : "=r"(a) : "l"(p));
    return a;
}
__device__ __forceinline__ void cp16(uint32_t dst, const void* src) {
    asm volatile("cp.async.cg.shared.global [%0], [%1], 16;" :: "r"(dst), "l"(src) : "memory");
}
__device__ __forceinline__ void ldsm4(uint32_t* r, uint32_t a) {
    asm volatile("ldmatrix.sync.aligned.m8n8.x4.shared.b16 {%0,%1,%2,%3}, [%4];"
                 : "=r"(r[0]), "=r"(r[1]), "=r"(r[2]), "=r"(r[3]) : "r"(a));
}
__device__ __forceinline__ void mma16816(float* c, const uint32_t* a, uint32_t b0, uint32_t b1) {
    asm volatile(
        "mma.sync.aligned.m16n8k16.row.col.f32.bf16.bf16.f32 "
        "{%0,%1,%2,%3}, {%4,%5,%6,%7}, {%8,%9}, {%0,%1,%2,%3};"
        : "+f"(c[0]), "+f"(c[1]), "+f"(c[2]), "+f"(c[3])
        : "r"(a[0]), "r"(a[1]), "r"(a[2]), "r"(a[3]), "r"(b0), "r"(b1));
}
// swizzled smem offset: 2 rows per 128B line, 16B chunk index ch (0..3)
__device__ __forceinline__ uint32_t swz(int m, int ch) {
    int l = m >> 1;
    int sub = ((m & 1) << 2) + ch;
    return (uint32_t)((l << 7) + ((sub ^ (l & 7)) << 4));
}

// ------------------------- bf16x3 mma.sync GEMM --------------------------
// C[M,N] = A[M,K] @ Bt[N,K]^T. CTA 128x128, 4 warps (64x64), Kc=32, 3 stages.
#define STG 32768
#define GEMM_SMEM (3 * STG)

__global__ void __launch_bounds__(128, 2) gemm_mma(
    const __nv_bfloat16* __restrict__ Ah, const __nv_bfloat16* __restrict__ Al,
    const __nv_bfloat16* __restrict__ Bh, const __nv_bfloat16* __restrict__ Bl,
    const float* __restrict__ bias, float* __restrict__ Cf,
    __nv_bfloat16* __restrict__ Chi, __nv_bfloat16* __restrict__ Clo,
    int N, int K, int act)
{
    extern __shared__ __align__(1024) char dsm[];
    const uint32_t smb = smem_u32(dsm);
    const int tid = threadIdx.x;
    const int bm = blockIdx.y * 128, bn = blockIdx.x * 128;
    const int wid = tid >> 5, L = tid & 31;
    const int wm = (wid >> 1) * 64;   // 0 / 64
    const int wn = (wid & 1) * 64;    // 0 / 64

    float acc[4][8][4];
#pragma unroll
    for (int i = 0; i < 4; i++)
#pragma unroll
        for (int j = 0; j < 8; j++)
#pragma unroll
            for (int q = 0; q < 4; q++) acc[i][j][q] = 0.f;

    const int matid = L >> 3;
    const int rA = (matid & 1) * 8 + (L & 7);
    const int cA = matid >> 1;
    const int rB = (L >> 4) * 8 + (L & 7);
    const int cB = (L >> 3) & 1;

    const int nkc = K / 32;
    auto load_stage = [&](int st, int kc) {
        uint32_t sb = smb + st * STG;
        size_t kb = (size_t)kc * 32;
#pragma unroll
        for (int t = 0; t < 4; t++) {
            int id = t * 128 + tid;          // 0..511
            int m = id >> 2, ch = id & 3;
            uint32_t dst = swz(m, ch);
            size_t sA = (size_t)(bm + m) * K + kb + ch * 8;
            size_t sB = (size_t)(bn + m) * K + kb + ch * 8;
            cp16(sb + dst,          Ah + sA);
            cp16(sb + 8192 + dst,   Al + sA);
            cp16(sb + 16384 + dst,  Bh + sB);
            cp16(sb + 24576 + dst,  Bl + sB);
        }
    };

#pragma unroll
    for (int s = 0; s < 3; s++) {
        load_stage(s, s);
        asm volatile("cp.async.commit_group;" ::: "memory");
    }

    for (int kc = 0; kc < nkc; kc++) {
        asm volatile("cp.async.wait_group 2;" ::: "memory");
        __syncthreads();
        uint32_t sb = smb + (kc % 3) * STG;
        uint32_t sAh = sb, sAl = sb + 8192, sBh = sb + 16384, sBl = sb + 24576;
#pragma unroll
        for (int ks = 0; ks < 2; ks++) {
            uint32_t ah[4][4], al[4][4], bh[4][4], bl[4][4];
#pragma unroll
            for (int mt = 0; mt < 4; mt++) {
                uint32_t off = swz(wm + mt * 16 + rA, ks * 2 + cA);
                ldsm4(ah[mt], sAh + off);
                ldsm4(al[mt], sAl + off);
            }
#pragma unroll
            for (int bt = 0; bt < 4; bt++) {
                uint32_t off = swz(wn + bt * 16 + rB, ks * 2 + cB);
                ldsm4(bh[bt], sBh + off);
                ldsm4(bl[bt], sBl + off);
            }
#pragma unroll
            for (int mt = 0; mt < 4; mt++)
#pragma unroll
                for (int nt = 0; nt < 8; nt++) {
                    int bt = nt >> 1, j = (nt & 1) * 2;
                    mma16816(acc[mt][nt], ah[mt], bh[bt][j], bh[bt][j + 1]);
                    mma16816(acc[mt][nt], ah[mt], bl[bt][j], bl[bt][j + 1]);
                    mma16816(acc[mt][nt], al[mt], bh[bt][j], bh[bt][j + 1]);
                }
        }
        __syncthreads();
        if (kc + 3 < nkc) load_stage(kc % 3, kc + 3);
        asm volatile("cp.async.commit_group;" ::: "memory");
    }

    // epilogue
#pragma unroll
    for (int mt = 0; mt < 4; mt++)
#pragma unroll
        for (int nt = 0; nt < 8; nt++) {
            int c0 = bn + wn + nt * 8 + (L & 3) * 2;
            float b0 = (act > 0) ? bias[c0] : 0.f;
            float b1 = (act > 0) ? bias[c0 + 1] : 0.f;
#pragma unroll
            for (int h = 0; h < 2; h++) {
                int row = bm + wm + mt * 16 + (L >> 2) + h * 8;
                float v0 = acc[mt][nt][h * 2 + 0] + b0;
                float v1 = acc[mt][nt][h * 2 + 1] + b1;
                if (act == 2) {
                    float t0 = v0 * v0 * v0, t1 = v1 * v1 * v1;
                    v0 = 0.5f * v0 * (1.f + tanhf(0.7978845608028654f * (v0 + 0.044715f * t0)));
                    v1 = 0.5f * v1 * (1.f + tanhf(0.7978845608028654f * (v1 + 0.044715f * t1)));
                }
                size_t idx = (size_t)row * N + c0;
                if (Cf) *reinterpret_cast<float2*>(Cf + idx) = make_float2(v0, v1);
                if (Chi) {
                    __nv_bfloat162 hh, ll;
                    hh.x = __float2bfloat16_rn(v0);
                    hh.y = __float2bfloat16_rn(v1);
                    ll.x = __float2bfloat16_rn(v0 - __bfloat162float(hh.x));
                    ll.y = __float2bfloat16_rn(v1 - __bfloat162float(hh.y));
                    *reinterpret_cast<__nv_bfloat162*>(Chi + idx) = hh;
                    *reinterpret_cast<__nv_bfloat162*>(Clo + idx) = ll;
                }
            }
        }
}

// ------------------------- small kernels ---------------------------------
__global__ void conv_split(const float* __restrict__ in, __nv_bfloat16* __restrict__ hi,
                           __nv_bfloat16* __restrict__ lo, size_t n4) {
    size_t i = (size_t)blockIdx.x * blockDim.x + threadIdx.x;
    if (i >= n4) return;
    float4 v = ((const float4*)in)[i];
    float vv[4] = {v.x, v.y, v.z, v.w};
#pragma unroll
    for (int j = 0; j < 4; j++) {
        __nv_bfloat16 h = __float2bfloat16_rn(vv[j]);
        hi[i * 4 + j] = h;
        lo[i * 4 + j] = __float2bfloat16_rn(vv[j] - __bfloat162float(h));
    }
}

__global__ void wconv_t(const float* __restrict__ W, __nv_bfloat16* __restrict__ Th,
                        __nv_bfloat16* __restrict__ Tl, int K, int N) {
    __shared__ float t[32][33];
    int n0 = blockIdx.x * 32, k0 = blockIdx.y * 32;
    int tx = threadIdx.x, ty = threadIdx.y;
#pragma unroll
    for (int j = 0; j < 4; j++)
        t[ty + j * 8][tx] = W[(size_t)(k0 + ty + j * 8) * N + n0 + tx];
    __syncthreads();
#pragma unroll
    for (int j = 0; j < 4; j++) {
        float v = t[tx][ty + j * 8];
        __nv_bfloat16 h = __float2bfloat16_rn(v);
        size_t idx = (size_t)(n0 + ty + j * 8) * K + k0 + tx;
        Th[idx] = h;
        Tl[idx] = __float2bfloat16_rn(v - __bfloat162float(h));
    }
}

__global__ void scan_p1(const float* __restrict__ P) {
    int idx = blockIdx.x * blockDim.x + threadIdx.x;
    int ch = idx & 2047, ck = idx >> 11;
    int b = ch >> 10, d = ch & 1023;
    const float* p = P + ((size_t)(b * Sz + ck * CLEN)) * NP;
    float hr = 0, hi = 0, pr = 1, pi = 0;
    for (int t = 0; t < CLEN; t++) {
        const float* r = p + (size_t)t * NP;
        float ar = r[3072 + d], ai = r[4096 + d];
        float kv = r[1024 + d] * r[2048 + d];
        float mag = sqrtf(fmaf(ar, ar, ai * ai));
        float s = 1.f / (1.f + __expf(-mag));
        float inv = s / fmaxf(mag, 1e-30f);
        float arr = ar * inv, aii = ai * inv;
        float nhr = fmaf(arr, hr, fmaf(-aii, hi, kv));
        float nhi = fmaf(arr, hi, aii * hr);
        hr = nhr; hi = nhi;
        float npr = arr * pr - aii * pi, npi = arr * pi + aii * pr;
        pr = npr; pi = npi;
    }
    s_apr[idx] = pr; s_api[idx] = pi; s_hr[idx] = hr; s_hi[idx] = hi;
}

__global__ void scan_p2() {
    int ch = blockIdx.x * blockDim.x + threadIdx.x;
    if (ch >= 2048) return;
    float cr = 0, ci = 0;
    for (int ck = 0; ck < NCH; ck++) {
        int i = ck * 2048 + ch;
        s_cr[i] = cr; s_ci[i] = ci;
        float pr = s_apr[i], pi = s_api[i];
        float ncr = fmaf(pr, cr, -pi * ci) + s_hr[i];
        float nci = fmaf(pr, ci,  pi * cr) + s_hi[i];
        cr = ncr; ci = nci;
    }
}

__global__ void scan_p3(const float* __restrict__ P,
                        __nv_bfloat16* __restrict__ yh, __nv_bfloat16* __restrict__ yl) {
    int idx = blockIdx.x * blockDim.x + threadIdx.x;
    int ch = idx & 2047, ck = idx >> 11;
    int b = ch >> 10, d = ch & 1023;
    size_t row0 = (size_t)(b * Sz + ck * CLEN);
    const float* p = P + row0 * NP;
    float hr = s_cr[idx], hi = s_ci[idx];
    for (int t = 0; t < CLEN; t++) {
        const float* r = p + (size_t)t * NP;
        float ar = r[3072 + d], ai = r[4096 + d];
        float kv = r[1024 + d] * r[2048 + d];
        float mag = sqrtf(fmaf(ar, ar, ai * ai));
        float s = 1.f / (1.f + __expf(-mag));
        float inv = s / fmaxf(mag, 1e-30f);
        float arr = ar * inv, aii = ai * inv;
        float nhr = fmaf(arr, hr, fmaf(-aii, hi, kv));
        float nhi = fmaf(arr, hi, aii * hr);
        hr = nhr; hi = nhi;
        float g = r[5120 + d];
        float sil = g / (1.f + __expf(-g));
        float yv = r[d] * hr * sil;
        __nv_bfloat16 h16 = __float2bfloat16_rn(yv);
        size_t o = (row0 + t) * Dz + d;
        yh[o] = h16;
        yl[o] = __float2bfloat16_rn(yv - __bfloat162float(h16));
    }
}

__global__ __launch_bounds__(256) void add_ln_kernel(
    const float* __restrict__ x, const float* __restrict__ res,
    const float* __restrict__ scale, const float* __restrict__ bias,
    float* __restrict__ out, __nv_bfloat16* __restrict__ oh, __nv_bfloat16* __restrict__ ol)
{
    __shared__ float red[8];
    int row = blockIdx.x, tid = threadIdx.x;
    const float* xr = x + (size_t)row * Dz;
    const float* rr = res + (size_t)row * Dz;
    float vals[4], sum = 0.f;
#pragma unroll
    for (int j = 0; j < 4; j++) { vals[j] = xr[tid + j * 256] + rr[tid + j * 256]; sum += vals[j]; }
#pragma unroll
    for (int o = 16; o > 0; o >>= 1) sum += __shfl_xor_sync(~0u, sum, o);
    if ((tid & 31) == 0) red[tid >> 5] = sum;
    __syncthreads();
    float tot = 0.f;
#pragma unroll
    for (int w = 0; w < 8; w++) tot += red[w];
    float mean = tot * (1.f / Dz);
    float vs = 0.f;
#pragma unroll
    for (int j = 0; j < 4; j++) { float dd = vals[j] - mean; vs += dd * dd; }
#pragma unroll
    for (int o = 16; o > 0; o >>= 1) vs += __shfl_xor_sync(~0u, vs, o);
    __syncthreads();
    if ((tid & 31) == 0) red[tid >> 5] = vs;
    __syncthreads();
    float vt = 0.f;
#pragma unroll
    for (int w = 0; w < 8; w++) vt += red[w];
    float rstd = rsqrtf(vt * (1.f / Dz) + 1e-6f);
#pragma unroll
    for (int j = 0; j < 4; j++) {
        int col = tid + j * 256;
        float v = (vals[j] - mean) * rstd * scale[col] + bias[col];
        size_t idx = (size_t)row * Dz + col;
        out[idx] = v;
        if (oh) {
            __nv_bfloat16 h = __float2bfloat16_rn(v);
            oh[idx] = h;
            ol[idx] = __float2bfloat16_rn(v - __bfloat162float(h));
        }
    }
}

// ------------------------- host ------------------------------------------
static void rungemm(const __nv_bfloat16* Ah, const __nv_bfloat16* Al, int K,
                    const __nv_bfloat16* Bh, const __nv_bfloat16* Bl, int N,
                    const float* bias, float* Cf, __nv_bfloat16* Chi, __nv_bfloat16* Clo, int act) {
    dim3 g(N / 128, Mz / 128);
    gemm_mma<<<g, 128, GEMM_SMEM>>>(Ah, Al, Bh, Bl, bias, Cf, Chi, Clo, N, K, act);
}

extern "C" void kernel_launch(void* const* d_in, const int* in_sizes, int n_in,
                              void* d_out, int out_size)
{
    const float* x    = (const float*)d_in[0];
    const float* Wq   = (const float*)d_in[1];
    const float* Wk   = (const float*)d_in[2];
    const float* Wv   = (const float*)d_in[3];
    const float* Wa   = (const float*)d_in[4];
    const float* Wg   = (const float*)d_in[5];
    const float* Wo   = (const float*)d_in[6];
    const float* ln1s = (const float*)d_in[7];
    const float* ln1b = (const float*)d_in[8];
    const float* W1   = (const float*)d_in[9];
    const float* b1   = (const float*)d_in[10];
    const float* W2   = (const float*)d_in[11];
    const float* b2   = (const float*)d_in[12];
    const float* ln2s = (const float*)d_in[13];
    const float* ln2b = (const float*)d_in[14];
    float* out = (float*)d_out;

    static int inited = 0;
    if (!inited) {
        cudaFuncSetAttribute(gemm_mma, cudaFuncAttributeMaxDynamicSharedMemorySize, GEMM_SMEM);
        inited = 1;
    }

    float *P, *Yo, *U, *O2;
    __nv_bfloat16 *xh, *xl, *yh, *yl, *uh, *ul, *Hh, *Hl;
    __nv_bfloat16 *WcH, *WcL, *WoH, *WoL, *W1H, *W1L, *W2H, *W2L;
    cudaGetSymbolAddress((void**)&P,  g_P);
    cudaGetSymbolAddress((void**)&Yo, g_Yo);
    cudaGetSymbolAddress((void**)&U,  g_U);
    cudaGetSymbolAddress((void**)&O2, g_O2);
    cudaGetSymbolAddress((void**)&xh, g_xh);  cudaGetSymbolAddress((void**)&xl, g_xl);
    cudaGetSymbolAddress((void**)&yh, g_yh);  cudaGetSymbolAddress((void**)&yl, g_yl);
    cudaGetSymbolAddress((void**)&uh, g_uh);  cudaGetSymbolAddress((void**)&ul, g_ul);
    cudaGetSymbolAddress((void**)&Hh, g_Hh);  cudaGetSymbolAddress((void**)&Hl, g_Hl);
    cudaGetSymbolAddress((void**)&WcH, g_Wc_h); cudaGetSymbolAddress((void**)&WcL, g_Wc_l);
    cudaGetSymbolAddress((void**)&WoH, g_Wo_h); cudaGetSymbolAddress((void**)&WoL, g_Wo_l);
    cudaGetSymbolAddress((void**)&W1H, g_W1_h); cudaGetSymbolAddress((void**)&W1L, g_W1_l);
    cudaGetSymbolAddress((void**)&W2H, g_W2_h); cudaGetSymbolAddress((void**)&W2L, g_W2_l);

    dim3 wb(32, 8);
    wconv_t<<<dim3(32, 32),  wb>>>(Wq, WcH,                       WcL,                       Dz, Dz);
    wconv_t<<<dim3(32, 32),  wb>>>(Wk, WcH + 1024 * 1024,         WcL + 1024 * 1024,         Dz, Dz);
    wconv_t<<<dim3(32, 32),  wb>>>(Wv, WcH + 2048 * 1024,         WcL + 2048 * 1024,         Dz, Dz);
    wconv_t<<<dim3(64, 32),  wb>>>(Wa, WcH + 3072 * 1024,         WcL + 3072 * 1024,         Dz, 2 * Dz);
    wconv_t<<<dim3(32, 32),  wb>>>(Wg, WcH + (size_t)5120 * 1024, WcL + (size_t)5120 * 1024, Dz, Dz);
    wconv_t<<<dim3(32, 32),  wb>>>(Wo, WoH, WoL, Dz, Dz);
    wconv_t<<<dim3(128, 32), wb>>>(W1, W1H, W1L, Dz, Fz);
    wconv_t<<<dim3(32, 128), wb>>>(W2, W2H, W2L, Fz, Dz);
    conv_split<<<(Mz * Dz / 4 + 255) / 256, 256>>>(x, xh, xl, (size_t)Mz * Dz / 4);

    rungemm(xh, xl, Dz, WcH, WcL, NP, nullptr, P, nullptr, nullptr, 0);
    scan_p1<<<256, 256>>>(P);
    scan_p2<<<8, 256>>>();
    scan_p3<<<256, 256>>>(P, yh, yl);
    rungemm(yh, yl, Dz, WoH, WoL, Dz, nullptr, Yo, nullptr, nullptr, 0);
    add_ln_kernel<<<Mz, 256>>>(Yo, x, ln1s, ln1b, U, uh, ul);
    rungemm(uh, ul, Dz, W1H, W1L, Fz, b1, nullptr, Hh, Hl, 2);
    rungemm(Hh, Hl, Fz, W2H, W2L, Dz, b2, O2, nullptr, nullptr, 1);
    add_ln_kernel<<<Mz, 256>>>(O2, U, ln2s, ln2b, out, nullptr, nullptr);
}